// round 5
// baseline (speedup 1.0000x reference)
#include <cuda_runtime.h>
#include <cuda_bf16.h>

#define BB 4
#define HH 16
#define SS 4096
#define DD 64
#define BH (BB*HH)
#define SPLIT 8
#define RR 4
#define SPLITX (SPLIT*RR)       // 32 partials per head
#define ROWS_P1 (SS/SPLIT)      // 512
#define CHUNK 16
#define NCH (ROWS_P1/CHUNK)     // 32
#define P2_TILE 256
#define KEPS 0.001f

typedef unsigned long long ull;

// Scratch (device globals: no allocs allowed)
__device__ float g_kv[BH][SPLITX][DD * DD];
__device__ float g_ksum[BH][SPLITX][DD];
__device__ float g_kvf[BH][DD * DD];
__device__ float g_ksumf[BH][DD];

// ---- packed fp32x2 helpers (sm_103a FFMA2 — only via PTX) ----
__device__ __forceinline__ ull ffma2(ull a, ull b, ull c) {
    ull d;
    asm("fma.rn.f32x2 %0, %1, %2, %3;" : "=l"(d) : "l"(a), "l"(b), "l"(c));
    return d;
}
__device__ __forceinline__ ull pack2(float x) {
    ull d;
    asm("mov.b64 %0, {%1, %1};" : "=l"(d) : "f"(x));
    return d;
}
__device__ __forceinline__ ull packf2(float x, float y) {
    ull d;
    asm("mov.b64 %0, {%1, %2};" : "=l"(d) : "f"(x), "f"(y));
    return d;
}
__device__ __forceinline__ float2 unpack2(ull a) {
    float2 r;
    asm("mov.b64 {%0, %1}, %2;" : "=f"(r.x), "=f"(r.y) : "l"(a));
    return r;
}

// ---------------------------------------------------------------------------
// Pass 1: kv[d][e] += k'[r][d]*v[r][e]; k stored in smem as DUPLICATE-PACKED
// pairs so the FFMA2 broadcast operand comes straight from LDS (no pack2 in
// the mainloop). rr = tid>>6 row-split -> own partial, no in-block reduction.
// ksum: one d per thread over its rr rows (balanced across all warps).
// ---------------------------------------------------------------------------
__global__ __launch_bounds__(256, 2) void perf_pass1(
    const float* __restrict__ K,
    const float* __restrict__ V,
    const float* __restrict__ mask)
{
    const int bh = blockIdx.x / SPLIT;
    const int sp = blockIdx.x % SPLIT;
    const int b  = bh / HH;

    const float* Kp = K + (size_t)bh * SS * DD + (size_t)sp * ROWS_P1 * DD;
    const float* Vp = V + (size_t)bh * SS * DD + (size_t)sp * ROWS_P1 * DD;
    const float* Mp = mask + (size_t)b * SS + (size_t)sp * ROWS_P1;

    __shared__ ull   kdub[2][CHUNK][DD];   // packed duplicate k' pairs (16KB)
    __shared__ float vs[2][CHUNK][DD];     // 8KB

    const int tid = threadIdx.x;
    const int eq = tid & 7;
    const int dq = (tid >> 3) & 7;
    const int rr = tid >> 6;
    const int dks = tid & 63;           // ksum d for this thread
    const int srow = tid >> 4;
    const int scol = (tid & 15) * 4;

    ull acc[8][4];
#pragma unroll
    for (int i = 0; i < 8; i++)
#pragma unroll
        for (int j = 0; j < 4; j++) acc[i][j] = 0ULL;
    float ksacc = 0.f;

    float4 kreg = *reinterpret_cast<const float4*>(&Kp[(size_t)srow * DD + scol]);
    float4 vreg = *reinterpret_cast<const float4*>(&Vp[(size_t)srow * DD + scol]);
    float  mreg = Mp[srow];

    for (int c = 0; c < NCH; c++) {
        const int buf = c & 1;
        // featurize + mask + duplicate-pack on the way into smem
        ulonglong2 d0, d1;
        d0.x = pack2((fmaxf(kreg.x, 0.f) + KEPS) * mreg);
        d0.y = pack2((fmaxf(kreg.y, 0.f) + KEPS) * mreg);
        d1.x = pack2((fmaxf(kreg.z, 0.f) + KEPS) * mreg);
        d1.y = pack2((fmaxf(kreg.w, 0.f) + KEPS) * mreg);
        ulonglong2* kd = reinterpret_cast<ulonglong2*>(&kdub[buf][srow][scol]);
        kd[0] = d0; kd[1] = d1;
        *reinterpret_cast<float4*>(&vs[buf][srow][scol]) = vreg;
        __syncthreads();

        if (c + 1 < NCH) {
            const size_t off = (size_t)(c + 1) * CHUNK * DD + (size_t)srow * DD + scol;
            kreg = *reinterpret_cast<const float4*>(&Kp[off]);
            vreg = *reinterpret_cast<const float4*>(&Vp[off]);
            mreg = Mp[(c + 1) * CHUNK + srow];
        }

        // ksum: this thread's d over its rr rows (low half of packed element)
        const float* kflat = reinterpret_cast<const float*>(&kdub[buf][0][0]);
#pragma unroll
        for (int r0 = 0; r0 < CHUNK; r0 += RR)
            ksacc += kflat[((r0 + rr) * DD + dks) * 2];

#pragma unroll
        for (int r0 = 0; r0 < CHUNK; r0 += RR) {
            const int r = r0 + rr;
            const ulonglong2* kp = reinterpret_cast<const ulonglong2*>(&kdub[buf][r][dq * 8]);
            const ulonglong2 k01 = kp[0], k23 = kp[1], k45 = kp[2], k67 = kp[3];
            const ulonglong2 va = *reinterpret_cast<const ulonglong2*>(&vs[buf][r][eq * 4]);
            const ulonglong2 vb = *reinterpret_cast<const ulonglong2*>(&vs[buf][r][eq * 4 + 32]);
            const ull kk[8] = {k01.x, k01.y, k23.x, k23.y, k45.x, k45.y, k67.x, k67.y};
#pragma unroll
            for (int i = 0; i < 8; i++) {
                acc[i][0] = ffma2(kk[i], va.x, acc[i][0]);
                acc[i][1] = ffma2(kk[i], va.y, acc[i][1]);
                acc[i][2] = ffma2(kk[i], vb.x, acc[i][2]);
                acc[i][3] = ffma2(kk[i], vb.y, acc[i][3]);
            }
        }
    }

    // write this rr-group's partial
    float* kvp = g_kv[bh][(sp << 2) | rr];
#pragma unroll
    for (int i = 0; i < 8; i++) {
        ull* row = reinterpret_cast<ull*>(kvp + (size_t)(dq * 8 + i) * DD);
        row[eq * 2]          = acc[i][0];
        row[eq * 2 + 1]      = acc[i][1];
        row[16 + eq * 2]     = acc[i][2];
        row[16 + eq * 2 + 1] = acc[i][3];
    }
    g_ksum[bh][(sp << 2) | rr][dks] = ksacc;
}

// ---------------------------------------------------------------------------
// Reduce: sum 32 kv partials + 32 ksum partials per head.
// ---------------------------------------------------------------------------
__global__ __launch_bounds__(256) void perf_reduce()
{
    const int bh = blockIdx.x >> 2;
    const int qt = blockIdx.x & 3;
    const int tid = threadIdx.x;
    const int idx = qt * 1024 + tid * 4;

    float4 s = make_float4(0.f, 0.f, 0.f, 0.f);
#pragma unroll
    for (int p = 0; p < SPLITX; p++) {
        const float4 v = *reinterpret_cast<const float4*>(&g_kv[bh][p][idx]);
        s.x += v.x; s.y += v.y; s.z += v.z; s.w += v.w;
    }
    *reinterpret_cast<float4*>(&g_kvf[bh][idx]) = s;

    if (qt == 0 && tid < DD) {
        float t = 0.f;
#pragma unroll
        for (int p = 0; p < SPLITX; p++) t += g_ksum[bh][p][tid];
        g_ksumf[bh][tid] = t;
    }
}

// ---------------------------------------------------------------------------
// Pass 2: out[s,e] = (q'[s,:] . kv[:,e]) / (q'[s,:] . ksum)
// kv pairs for a 4-d group hoisted to regs; q streamed one row at a time
// (keeps live regs ~110, no spills at 2 blocks/SM). Rotation swizzle on qs.
// ---------------------------------------------------------------------------
__global__ __launch_bounds__(256, 2) void perf_pass2(
    const float* __restrict__ Q,
    float* __restrict__ O)
{
    extern __shared__ float sm[];
    float* kv   = sm;                     // 4096
    float* qs   = sm + DD * DD;           // P2_TILE * 64
    float* ksum = qs + P2_TILE * DD;      // 64

    const int bh   = blockIdx.x >> 4;
    const int tile = blockIdx.x & 15;
    const int tid  = threadIdx.x;
    const int eq   = tid & 7;
    const int rq   = tid >> 3;

#pragma unroll
    for (int i = 0; i < 4; i++) {
        const int idx = tid * 4 + i * 1024;
        *reinterpret_cast<float4*>(&kv[idx]) =
            *reinterpret_cast<const float4*>(&g_kvf[bh][idx]);
    }
    if (tid < DD) ksum[tid] = g_ksumf[bh][tid];

    const float* Qp = Q + (size_t)bh * SS * DD + (size_t)tile * P2_TILE * DD;
    float*       Op = O + (size_t)bh * SS * DD + (size_t)tile * P2_TILE * DD;
#pragma unroll
    for (int i = 0; i < 16; i++) {
        const int idx = tid * 4 + i * 1024;
        float4 v = *reinterpret_cast<const float4*>(&Qp[idx]);
        v.x = fmaxf(v.x, 0.f) + KEPS;
        v.y = fmaxf(v.y, 0.f) + KEPS;
        v.z = fmaxf(v.z, 0.f) + KEPS;
        v.w = fmaxf(v.w, 0.f) + KEPS;
        const int r = idx >> 6;
        const int c = idx & 63;
        const int rot = ((r >> 3) & 3) * 4;
        *reinterpret_cast<float4*>(&qs[r * DD + ((c + rot) & 63)]) = v;
    }
    __syncthreads();

    ull acc[8][4];
#pragma unroll
    for (int i = 0; i < 8; i++)
#pragma unroll
        for (int j = 0; j < 4; j++) acc[i][j] = 0ULL;
    ull dacc[8];
#pragma unroll
    for (int i = 0; i < 8; i++) dacc[i] = 0ULL;

    const int rot = (rq & 3) * 4;

    for (int d = 0; d < DD; d += 4) {
        const ulonglong2 ks2 = *reinterpret_cast<const ulonglong2*>(&ksum[d]);
        const int col = (d + rot) & 63;

        // hoist kv pairs for the whole 4-d group
        ulonglong2 kva[4], kvb[4];
#pragma unroll
        for (int dd = 0; dd < 4; dd++) {
            const float* kvrow = &kv[(size_t)(d + dd) * DD];
            kva[dd] = *reinterpret_cast<const ulonglong2*>(&kvrow[eq * 4]);
            kvb[dd] = *reinterpret_cast<const ulonglong2*>(&kvrow[eq * 4 + 32]);
        }

        // stream q one row at a time
#pragma unroll
        for (int i = 0; i < 8; i++) {
            const float4 q4 = *reinterpret_cast<const float4*>(
                &qs[(rq * 8 + i) * DD + col]);
            dacc[i] = ffma2(packf2(q4.x, q4.y), ks2.x, dacc[i]);
            dacc[i] = ffma2(packf2(q4.z, q4.w), ks2.y, dacc[i]);
            const float qv[4] = {q4.x, q4.y, q4.z, q4.w};
#pragma unroll
            for (int dd = 0; dd < 4; dd++) {
                const ull qb = pack2(qv[dd]);
                acc[i][0] = ffma2(qb, kva[dd].x, acc[i][0]);
                acc[i][1] = ffma2(qb, kva[dd].y, acc[i][1]);
                acc[i][2] = ffma2(qb, kvb[dd].x, acc[i][2]);
                acc[i][3] = ffma2(qb, kvb[dd].y, acc[i][3]);
            }
        }
    }

#pragma unroll
    for (int i = 0; i < 8; i++) {
        const float2 dp = unpack2(dacc[i]);
        const float inv = 1.0f / (dp.x + dp.y);
        const float2 a0 = unpack2(acc[i][0]);
        const float2 a1 = unpack2(acc[i][1]);
        const float2 a2 = unpack2(acc[i][2]);
        const float2 a3 = unpack2(acc[i][3]);
        const int row = rq * 8 + i;
        float4 o0 = make_float4(a0.x * inv, a0.y * inv, a1.x * inv, a1.y * inv);
        float4 o1 = make_float4(a2.x * inv, a2.y * inv, a3.x * inv, a3.y * inv);
        *reinterpret_cast<float4*>(&Op[(size_t)row * DD + eq * 4])      = o0;
        *reinterpret_cast<float4*>(&Op[(size_t)row * DD + eq * 4 + 32]) = o1;
    }
}

#define SMEM_P2 ((DD * DD + P2_TILE * DD + DD) * (int)sizeof(float))

extern "C" void kernel_launch(void* const* d_in, const int* in_sizes, int n_in,
                              void* d_out, int out_size)
{
    const float* Q = (const float*)d_in[0];
    const float* K = (const float*)d_in[1];
    const float* V = (const float*)d_in[2];
    const float* M = (const float*)d_in[3];
    float* O = (float*)d_out;

    cudaFuncSetAttribute(perf_pass2, cudaFuncAttributeMaxDynamicSharedMemorySize, SMEM_P2);

    perf_pass1<<<BH * SPLIT, 256>>>(K, V, M);
    perf_reduce<<<BH * 4, 256>>>();
    perf_pass2<<<BH * 16, 256, SMEM_P2>>>(Q, O);
}

// round 6
// speedup vs baseline: 1.0923x; 1.0923x over previous
#include <cuda_runtime.h>
#include <cuda_bf16.h>

#define BB 4
#define HH 16
#define SS 4096
#define DD 64
#define BH (BB*HH)
#define SPLIT 16
#define RR 2
#define PKV (SPLIT*RR)          // 32 kv partials per head
#define PKS (SPLIT*4)           // 64 ksum partials per head
#define ROWS_P1 (SS/SPLIT)      // 256
#define CHUNK 16
#define NCH (ROWS_P1/CHUNK)     // 16
#define P2_TILE 128
#define KEPS 0.001f

typedef unsigned long long ull;

// Scratch (device globals: no allocs allowed)
__device__ float g_kv[BH][PKV][DD * DD];
__device__ float g_ksum[BH][PKS][DD];
__device__ float g_kvf[BH][DD * DD];
__device__ float g_ksumf[BH][DD];

// ---- packed fp32x2 helpers (sm_103a FFMA2 — only via PTX) ----
__device__ __forceinline__ ull ffma2(ull a, ull b, ull c) {
    ull d;
    asm("fma.rn.f32x2 %0, %1, %2, %3;" : "=l"(d) : "l"(a), "l"(b), "l"(c));
    return d;
}
__device__ __forceinline__ ull pack2(float x) {
    ull d;
    asm("mov.b64 %0, {%1, %1};" : "=l"(d) : "f"(x));
    return d;
}
__device__ __forceinline__ ull packf2(float x, float y) {
    ull d;
    asm("mov.b64 %0, {%1, %2};" : "=l"(d) : "f"(x), "f"(y));
    return d;
}
__device__ __forceinline__ float2 unpack2(ull a) {
    float2 r;
    asm("mov.b64 {%0, %1}, %2;" : "=f"(r.x), "=f"(r.y) : "l"(a));
    return r;
}

// ---------------------------------------------------------------------------
// Pass 1: kv[d][e] += k'[r][d]*v[r][e]. Tile 4d x 8e per thread (32 acc regs)
// -> 3 blocks/SM, 6 warps/SMSP. rr=tid>>7 row-split (2 partials per (sp)).
// ksum: thread (g4, dks) sums d=dks over rows r%4==g4 (stride-1, balanced).
// ---------------------------------------------------------------------------
__global__ __launch_bounds__(256, 3) void perf_pass1(
    const float* __restrict__ K,
    const float* __restrict__ V,
    const float* __restrict__ mask)
{
    const int bh = blockIdx.x / SPLIT;
    const int sp = blockIdx.x % SPLIT;
    const int b  = bh / HH;

    const float* Kp = K + (size_t)bh * SS * DD + (size_t)sp * ROWS_P1 * DD;
    const float* Vp = V + (size_t)bh * SS * DD + (size_t)sp * ROWS_P1 * DD;
    const float* Mp = mask + (size_t)b * SS + (size_t)sp * ROWS_P1;

    __shared__ float ks[2][CHUNK][DD];
    __shared__ float vs[2][CHUNK][DD];

    const int tid = threadIdx.x;
    const int eq  = tid & 7;
    const int dq  = (tid >> 3) & 15;
    const int rr  = tid >> 7;           // 0/1 row split
    const int g4  = tid >> 6;           // 0..3 ksum row group
    const int dks = tid & 63;           // ksum d
    const int srow = tid >> 4;
    const int scol = (tid & 15) * 4;

    ull acc[4][4];
#pragma unroll
    for (int i = 0; i < 4; i++)
#pragma unroll
        for (int j = 0; j < 4; j++) acc[i][j] = 0ULL;
    float ksacc = 0.f;

    float4 kreg = *reinterpret_cast<const float4*>(&Kp[(size_t)srow * DD + scol]);
    float4 vreg = *reinterpret_cast<const float4*>(&Vp[(size_t)srow * DD + scol]);
    float  mreg = Mp[srow];

    for (int c = 0; c < NCH; c++) {
        const int buf = c & 1;
        float4 kf;
        kf.x = (fmaxf(kreg.x, 0.f) + KEPS) * mreg;
        kf.y = (fmaxf(kreg.y, 0.f) + KEPS) * mreg;
        kf.z = (fmaxf(kreg.z, 0.f) + KEPS) * mreg;
        kf.w = (fmaxf(kreg.w, 0.f) + KEPS) * mreg;
        *reinterpret_cast<float4*>(&ks[buf][srow][scol]) = kf;
        *reinterpret_cast<float4*>(&vs[buf][srow][scol]) = vreg;
        __syncthreads();

        if (c + 1 < NCH) {
            const size_t off = (size_t)(c + 1) * CHUNK * DD + (size_t)srow * DD + scol;
            kreg = *reinterpret_cast<const float4*>(&Kp[off]);
            vreg = *reinterpret_cast<const float4*>(&Vp[off]);
            mreg = Mp[(c + 1) * CHUNK + srow];
        }

        // balanced ksum: stride-1 float reads, 4 per chunk per thread
#pragma unroll
        for (int j = 0; j < 4; j++) ksacc += ks[buf][j * 4 + g4][dks];

#pragma unroll
        for (int r0 = 0; r0 < CHUNK; r0 += RR) {
            const int r = r0 + rr;
            const float4 ka = *reinterpret_cast<const float4*>(&ks[buf][r][dq * 4]);
            const ulonglong2 va = *reinterpret_cast<const ulonglong2*>(&vs[buf][r][eq * 4]);
            const ulonglong2 vb = *reinterpret_cast<const ulonglong2*>(&vs[buf][r][eq * 4 + 32]);
            const float kd[4] = {ka.x, ka.y, ka.z, ka.w};
#pragma unroll
            for (int i = 0; i < 4; i++) {
                const ull kp = pack2(kd[i]);
                acc[i][0] = ffma2(kp, va.x, acc[i][0]);
                acc[i][1] = ffma2(kp, va.y, acc[i][1]);
                acc[i][2] = ffma2(kp, vb.x, acc[i][2]);
                acc[i][3] = ffma2(kp, vb.y, acc[i][3]);
            }
        }
    }

    float* kvp = g_kv[bh][(sp << 1) | rr];
#pragma unroll
    for (int i = 0; i < 4; i++) {
        ull* row = reinterpret_cast<ull*>(kvp + (size_t)(dq * 4 + i) * DD);
        row[eq * 2]          = acc[i][0];
        row[eq * 2 + 1]      = acc[i][1];
        row[16 + eq * 2]     = acc[i][2];
        row[16 + eq * 2 + 1] = acc[i][3];
    }
    g_ksum[bh][(sp << 2) | g4][dks] = ksacc;
}

// ---------------------------------------------------------------------------
// Reduce: sum 32 kv partials + 64 ksum partials per head.
// ---------------------------------------------------------------------------
__global__ __launch_bounds__(256) void perf_reduce()
{
    const int bh = blockIdx.x >> 2;
    const int qt = blockIdx.x & 3;
    const int tid = threadIdx.x;
    const int idx = qt * 1024 + tid * 4;

    float4 s = make_float4(0.f, 0.f, 0.f, 0.f);
#pragma unroll
    for (int p = 0; p < PKV; p++) {
        const float4 v = *reinterpret_cast<const float4*>(&g_kv[bh][p][idx]);
        s.x += v.x; s.y += v.y; s.z += v.z; s.w += v.w;
    }
    *reinterpret_cast<float4*>(&g_kvf[bh][idx]) = s;

    if (qt == 0 && tid < DD) {
        float t = 0.f;
#pragma unroll
        for (int p = 0; p < PKS; p++) t += g_ksum[bh][p][tid];
        g_ksumf[bh][tid] = t;
    }
}

// ---------------------------------------------------------------------------
// Pass 2: out[s,e] = (q'[s,:] . kv[:,e]) / (q'[s,:] . ksum)
// Tile 4 rows x 8 e per thread (32 acc regs) -> 3 blocks/SM. P2_TILE=128.
// kv pairs hoisted per 4-d group; q streamed; rotation swizzle on qs.
// ---------------------------------------------------------------------------
__global__ __launch_bounds__(256, 3) void perf_pass2(
    const float* __restrict__ Q,
    float* __restrict__ O)
{
    extern __shared__ float sm[];
    float* kv   = sm;                     // 4096
    float* qs   = sm + DD * DD;           // P2_TILE*64 = 8192
    float* ksum = qs + P2_TILE * DD;      // 64

    const int bh   = blockIdx.x >> 5;
    const int tile = blockIdx.x & 31;
    const int tid  = threadIdx.x;
    const int eq   = tid & 7;
    const int rq   = tid >> 3;            // 0..31, rows rq*4..+3

#pragma unroll
    for (int i = 0; i < 4; i++) {
        const int idx = tid * 4 + i * 1024;
        *reinterpret_cast<float4*>(&kv[idx]) =
            *reinterpret_cast<const float4*>(&g_kvf[bh][idx]);
    }
    if (tid < DD) ksum[tid] = g_ksumf[bh][tid];

    const float* Qp = Q + (size_t)bh * SS * DD + (size_t)tile * P2_TILE * DD;
    float*       Op = O + (size_t)bh * SS * DD + (size_t)tile * P2_TILE * DD;
#pragma unroll
    for (int i = 0; i < 8; i++) {
        const int idx = tid * 4 + i * 1024;
        float4 v = *reinterpret_cast<const float4*>(&Qp[idx]);
        v.x = fmaxf(v.x, 0.f) + KEPS;
        v.y = fmaxf(v.y, 0.f) + KEPS;
        v.z = fmaxf(v.z, 0.f) + KEPS;
        v.w = fmaxf(v.w, 0.f) + KEPS;
        const int r = idx >> 6;
        const int c = idx & 63;
        const int rot = ((r >> 2) & 3) * 4;
        *reinterpret_cast<float4*>(&qs[r * DD + ((c + rot) & 63)]) = v;
    }
    __syncthreads();

    ull acc[4][4];
#pragma unroll
    for (int i = 0; i < 4; i++)
#pragma unroll
        for (int j = 0; j < 4; j++) acc[i][j] = 0ULL;
    ull dacc[4] = {0ULL, 0ULL, 0ULL, 0ULL};

    const int rot = (rq & 3) * 4;

    for (int d = 0; d < DD; d += 4) {
        const ulonglong2 ks2 = *reinterpret_cast<const ulonglong2*>(&ksum[d]);
        const int col = (d + rot) & 63;

        ulonglong2 kva[4], kvb[4];
#pragma unroll
        for (int dd = 0; dd < 4; dd++) {
            const float* kvrow = &kv[(size_t)(d + dd) * DD];
            kva[dd] = *reinterpret_cast<const ulonglong2*>(&kvrow[eq * 4]);
            kvb[dd] = *reinterpret_cast<const ulonglong2*>(&kvrow[eq * 4 + 32]);
        }

#pragma unroll
        for (int i = 0; i < 4; i++) {
            const float4 q4 = *reinterpret_cast<const float4*>(
                &qs[(rq * 4 + i) * DD + col]);
            dacc[i] = ffma2(packf2(q4.x, q4.y), ks2.x, dacc[i]);
            dacc[i] = ffma2(packf2(q4.z, q4.w), ks2.y, dacc[i]);
            const float qv[4] = {q4.x, q4.y, q4.z, q4.w};
#pragma unroll
            for (int dd = 0; dd < 4; dd++) {
                const ull qb = pack2(qv[dd]);
                acc[i][0] = ffma2(qb, kva[dd].x, acc[i][0]);
                acc[i][1] = ffma2(qb, kva[dd].y, acc[i][1]);
                acc[i][2] = ffma2(qb, kvb[dd].x, acc[i][2]);
                acc[i][3] = ffma2(qb, kvb[dd].y, acc[i][3]);
            }
        }
    }

#pragma unroll
    for (int i = 0; i < 4; i++) {
        const float2 dp = unpack2(dacc[i]);
        const float inv = 1.0f / (dp.x + dp.y);
        const float2 a0 = unpack2(acc[i][0]);
        const float2 a1 = unpack2(acc[i][1]);
        const float2 a2 = unpack2(acc[i][2]);
        const float2 a3 = unpack2(acc[i][3]);
        const int row = rq * 4 + i;
        float4 o0 = make_float4(a0.x * inv, a0.y * inv, a1.x * inv, a1.y * inv);
        float4 o1 = make_float4(a2.x * inv, a2.y * inv, a3.x * inv, a3.y * inv);
        *reinterpret_cast<float4*>(&Op[(size_t)row * DD + eq * 4])      = o0;
        *reinterpret_cast<float4*>(&Op[(size_t)row * DD + eq * 4 + 32]) = o1;
    }
}

#define SMEM_P2 ((DD * DD + P2_TILE * DD + DD) * (int)sizeof(float))

extern "C" void kernel_launch(void* const* d_in, const int* in_sizes, int n_in,
                              void* d_out, int out_size)
{
    const float* Q = (const float*)d_in[0];
    const float* K = (const float*)d_in[1];
    const float* V = (const float*)d_in[2];
    const float* M = (const float*)d_in[3];
    float* O = (float*)d_out;

    cudaFuncSetAttribute(perf_pass2, cudaFuncAttributeMaxDynamicSharedMemorySize, SMEM_P2);

    perf_pass1<<<BH * SPLIT, 256>>>(K, V, M);
    perf_reduce<<<BH * 4, 256>>>();
    perf_pass2<<<BH * 32, 256, SMEM_P2>>>(Q, O);
}